// round 2
// baseline (speedup 1.0000x reference)
#include <cuda_runtime.h>
#include <math.h>

#define BB 32
#define SS 8192
#define DD 256
#define HH 256

// scratch (device globals: allocation-free rule)
__device__ float g_inp[BB * HH];     // x @ W_in^T + b_in
__device__ float g_Wt[DD * HH];      // W_ctx transposed -> [d][h]
__device__ float g_att[BB * SS];     // attention logits (post 10*tanh)

// ---------------------------------------------------------------------------
// Kernel 1: inp[b,h] = b_in[h] + sum_d x[b,d] * W_in[h,d]
// ---------------------------------------------------------------------------
__global__ void k_inp(const float* __restrict__ x,
                      const float* __restrict__ W_in,
                      const float* __restrict__ b_in) {
    int b = blockIdx.x, h = threadIdx.x;
    __shared__ float xs[HH];
    xs[h] = x[b * HH + h];
    __syncthreads();
    float acc = b_in[h];
    const float* w = W_in + h * HH;
#pragma unroll 8
    for (int d0 = 0; d0 < HH; d0 += 4) {
        float4 w4 = *(const float4*)(w + d0);
        acc += xs[d0] * w4.x + xs[d0 + 1] * w4.y + xs[d0 + 2] * w4.z + xs[d0 + 3] * w4.w;
    }
    g_inp[b * HH + h] = acc;
}

// ---------------------------------------------------------------------------
// Kernel 2: Wt[d][h] = W_ctx[h][d]
// ---------------------------------------------------------------------------
__global__ void k_transpose(const float* __restrict__ W) {
    __shared__ float t[32][33];
    int h0 = blockIdx.x * 32, d0 = blockIdx.y * 32;
    t[threadIdx.y][threadIdx.x] = W[(h0 + threadIdx.y) * DD + d0 + threadIdx.x];
    __syncthreads();
    g_Wt[(d0 + threadIdx.y) * HH + h0 + threadIdx.x] = t[threadIdx.x][threadIdx.y];
}

// ---------------------------------------------------------------------------
// Kernel 3: fused GEMM (packed f32x2 FFMA2) + tanh-dot epilogue.
// Block = 64 seq rows x 256 h, K=256 in tiles of 32.
// Thread (tm = warp 0..7, tn = lane 0..31):
//   rows  m = tm + 8*i          (i = 0..7)
//   cols  n = 2*(tn + 32*jp)+q  (jp = 0..3, q = 0..1)  -- column pairs packed
// acc2[i][jp] is a f32x2 holding {acc(n_even), acc(n_odd)}.
// ---------------------------------------------------------------------------
#define TM 64
#define KT 32
__global__ __launch_bounds__(256) void k_main(const float* __restrict__ context,
                                              const float* __restrict__ b_ctx,
                                              const float* __restrict__ V) {
    __shared__ float2 As2[TM][KT];     // 16 KB, value-duplicated {v,v}
    __shared__ float  Bs[KT][HH];      // 32 KB, same bytes as Wt rows

    int b  = blockIdx.y;
    int m0 = blockIdx.x * TM;
    int tid = threadIdx.x;
    int tn = tid & 31;   // lane
    int tm = tid >> 5;   // warp

    // per-thread column metadata: n = 2*(tn + 32*jp) + q
    float vvp[4][2], ibp[4][2];
#pragma unroll
    for (int jp = 0; jp < 4; jp++) {
#pragma unroll
        for (int q = 0; q < 2; q++) {
            int n = 2 * (tn + 32 * jp) + q;
            vvp[jp][q] = V[n];
            ibp[jp][q] = g_inp[b * HH + n] + b_ctx[n];
        }
    }

    unsigned long long acc2[8][4];
#pragma unroll
    for (int i = 0; i < 8; i++)
#pragma unroll
        for (int jp = 0; jp < 4; jp++) acc2[i][jp] = 0ull;

    const float* ctx = context + ((long)b * SS + m0) * DD;

    for (int k0 = 0; k0 < DD; k0 += KT) {
        // A tile: 64 rows x 32 k, duplicated into float2 {v,v}
        {
            int idx = tid * 8;           // 2048 float2 elems / 256 thr = 8 each
            int row = idx >> 5;
            int col = idx & 31;
            float4 a0 = *(const float4*)(ctx + row * DD + k0 + col);
            float4 a1 = *(const float4*)(ctx + row * DD + k0 + col + 4);
            *(float4*)(&As2[row][col])     = make_float4(a0.x, a0.x, a0.y, a0.y);
            *(float4*)(&As2[row][col + 2]) = make_float4(a0.z, a0.z, a0.w, a0.w);
            *(float4*)(&As2[row][col + 4]) = make_float4(a1.x, a1.x, a1.y, a1.y);
            *(float4*)(&As2[row][col + 6]) = make_float4(a1.z, a1.z, a1.w, a1.w);
        }
        // B tile: 32 k x 256 n from pre-transposed Wt, coalesced float4
#pragma unroll
        for (int r = 0; r < 8; r++) {
            int f  = tid + 256 * r;
            int k  = f >> 6;
            int n4 = f & 63;
            float4 v4 = *(const float4*)(g_Wt + (k0 + k) * HH + n4 * 4);
            *(float4*)(&Bs[k][n4 * 4]) = v4;
        }
        __syncthreads();

#pragma unroll
        for (int k = 0; k < KT; k++) {
            unsigned long long a2[8], b2[4];
#pragma unroll
            for (int i = 0; i < 8; i++)
                a2[i] = *(const unsigned long long*)(&As2[tm + 8 * i][k]);   // broadcast LDS.64
#pragma unroll
            for (int jp = 0; jp < 4; jp++)
                b2[jp] = *(const unsigned long long*)(&Bs[k][2 * (tn + 32 * jp)]); // LDS.64, cf-free
#pragma unroll
            for (int i = 0; i < 8; i++)
#pragma unroll
                for (int jp = 0; jp < 4; jp++)
                    asm("fma.rn.f32x2 %0, %1, %2, %0;"
                        : "+l"(acc2[i][jp]) : "l"(a2[i]), "l"(b2[jp]));
        }
        __syncthreads();
    }

    // epilogue: per-row tanh-dot with V, warp reduction
#pragma unroll
    for (int i = 0; i < 8; i++) {
        float part = 0.f;
#pragma unroll
        for (int jp = 0; jp < 4; jp++) {
            unsigned int lo, hi;
            asm("mov.b64 {%0,%1}, %2;" : "=r"(lo), "=r"(hi) : "l"(acc2[i][jp]));
            part += vvp[jp][0] * tanhf(__uint_as_float(lo) + ibp[jp][0]);
            part += vvp[jp][1] * tanhf(__uint_as_float(hi) + ibp[jp][1]);
        }
#pragma unroll
        for (int off = 16; off; off >>= 1)
            part += __shfl_xor_sync(0xffffffffu, part, off);
        if (tn == 0)
            g_att[b * SS + m0 + tm + 8 * i] = 10.f * tanhf(part);
    }
}

// ---------------------------------------------------------------------------
// Kernel 4a: echo mask to output (wide grid for bandwidth)
// ---------------------------------------------------------------------------
__global__ void k_echo(const int* __restrict__ mask, float* __restrict__ out) {
    int i = blockIdx.x * blockDim.x + threadIdx.x;
    out[2 * BB + i] = mask[i] ? 1.f : 0.f;
}

// ---------------------------------------------------------------------------
// Kernel 4b: per-batch masked argmax + p = 1/sum(exp(att - max)).
// ---------------------------------------------------------------------------
__global__ __launch_bounds__(1024) void k_reduce(const int* __restrict__ mask,
                                                 float* __restrict__ out) {
    int b = blockIdx.x;
    int tid = threadIdx.x;
    __shared__ float smax[1024];
    __shared__ int   sidx[1024];

    float best = -INFINITY;
    int bidx = 0x7fffffff;
    for (int s = tid; s < SS; s += 1024) {
        if (mask[b * SS + s]) {
            float v = g_att[b * SS + s];
            if (v > best || (v == best && s < bidx)) { best = v; bidx = s; }
        }
    }
    smax[tid] = best; sidx[tid] = bidx;
    __syncthreads();
    for (int off = 512; off; off >>= 1) {
        if (tid < off) {
            float v = smax[tid + off]; int ix = sidx[tid + off];
            if (v > smax[tid] || (v == smax[tid] && ix < sidx[tid])) {
                smax[tid] = v; sidx[tid] = ix;
            }
        }
        __syncthreads();
    }
    float rowmax = smax[0];
    int rowidx = (rowmax == -INFINITY) ? 0 : sidx[0];
    __syncthreads();

    float se = 0.f;
    for (int s = tid; s < SS; s += 1024) {
        if (mask[b * SS + s]) se += expf(g_att[b * SS + s] - rowmax);
    }
    smax[tid] = se;
    __syncthreads();
    for (int off = 512; off; off >>= 1) {
        if (tid < off) smax[tid] += smax[tid + off];
        __syncthreads();
    }
    if (tid == 0) {
        out[b]      = (float)rowidx;
        out[BB + b] = 1.f / smax[0];
    }
}

// ---------------------------------------------------------------------------
extern "C" void kernel_launch(void* const* d_in, const int* in_sizes, int n_in,
                              void* d_out, int out_size) {
    const float* x      = (const float*)d_in[0];  // [32,256]
    const float* contex = (const float*)d_in[1];  // [32,8192,256]
    const int*   mask   = (const int*)  d_in[2];  // [32,8192]
    const float* W_in   = (const float*)d_in[3];  // [256,256]
    const float* b_in   = (const float*)d_in[4];  // [256]
    const float* W_ctx  = (const float*)d_in[5];  // [256,256]
    const float* b_ctx  = (const float*)d_in[6];  // [256]
    const float* V      = (const float*)d_in[7];  // [256]
    float* out = (float*)d_out;

    k_inp<<<BB, HH>>>(x, W_in, b_in);
    k_transpose<<<dim3(HH / 32, DD / 32), dim3(32, 32)>>>(W_ctx);
    k_main<<<dim3(SS / TM, BB), 256>>>(contex, b_ctx, V);
    k_echo<<<BB * SS / 256, 256>>>(mask, out);
    k_reduce<<<BB, 1024>>>(mask, out);
}

// round 5
// speedup vs baseline: 1.4846x; 1.4846x over previous
#include <cuda_runtime.h>
#include <cuda_bf16.h>
#include <math.h>
#include <stdint.h>

#define BB 32
#define SS 8192
#define DD 256
#define HH 256

// device-global scratch (allocation-free rule)
__device__ float g_inp[BB * HH];             // x @ W_in^T + b_in
__device__ __nv_bfloat16 g_Bh[HH * DD];      // W_ctx hi (bf16), [h][d]
__device__ __nv_bfloat16 g_Bl[HH * DD];      // W_ctx lo
__device__ float g_att[BB * SS];             // logits post 10*tanh

// ---------------------------------------------------------------------------
__device__ __forceinline__ uint32_t smem_u32(const void* p) {
    uint32_t a;
    asm("{ .reg .u64 t; cvta.to.shared.u64 t, %1; cvt.u32.u64 %0, t; }" : "=r"(a) : "l"(p));
    return a;
}
#define CP_ASYNC16(dst, src) \
    asm volatile("cp.async.cg.shared.global [%0], [%1], 16;" :: "r"(dst), "l"(src))
#define CP_COMMIT() asm volatile("cp.async.commit_group;" ::: "memory")
#define CP_WAIT0()  asm volatile("cp.async.wait_group 0;" ::: "memory")

#define LDSM4(r0, r1, r2, r3, a) \
    asm volatile("ldmatrix.sync.aligned.m8n8.x4.shared.b16 {%0,%1,%2,%3}, [%4];" \
        : "=r"(r0), "=r"(r1), "=r"(r2), "=r"(r3) : "r"(a))

#define MMA_BF16(c, A, b0, b1) \
    asm volatile("mma.sync.aligned.m16n8k16.row.col.f32.bf16.bf16.f32 " \
        "{%0,%1,%2,%3},{%4,%5,%6,%7},{%8,%9},{%0,%1,%2,%3};" \
        : "+f"((c)[0]), "+f"((c)[1]), "+f"((c)[2]), "+f"((c)[3]) \
        : "r"((A)[0]), "r"((A)[1]), "r"((A)[2]), "r"((A)[3]), "r"(b0), "r"(b1))

// ---------------------------------------------------------------------------
// Kernel 1: inp[b,h] = b_in[h] + sum_d x[b,d] * W_in[h,d]
// ---------------------------------------------------------------------------
__global__ void k_inp(const float* __restrict__ x, const float* __restrict__ W_in,
                      const float* __restrict__ b_in) {
    int b = blockIdx.x, h = threadIdx.x;
    __shared__ float xs[HH];
    xs[h] = x[b * HH + h];
    __syncthreads();
    float acc = b_in[h];
    const float* w = W_in + h * HH;
#pragma unroll 8
    for (int d0 = 0; d0 < HH; d0 += 4) {
        float4 w4 = *(const float4*)(w + d0);
        acc += xs[d0] * w4.x + xs[d0+1] * w4.y + xs[d0+2] * w4.z + xs[d0+3] * w4.w;
    }
    g_inp[b * HH + h] = acc;
}

// ---------------------------------------------------------------------------
// Kernel 2: split W_ctx fp32 -> bf16 hi/lo
// ---------------------------------------------------------------------------
__global__ void k_wsplit(const float* __restrict__ W) {
    int i = blockIdx.x * 256 + threadIdx.x;
    float v = W[i];
    __nv_bfloat16 h = __float2bfloat16_rn(v);
    g_Bh[i] = h;
    g_Bl[i] = __float2bfloat16_rn(v - __bfloat162float(h));
}

// ---------------------------------------------------------------------------
// Kernel 3: split-bf16 HMMA GEMM + fused tanh-dot epilogue.
// CTA: M=64 seq rows, N=256 (all h), K=256 in 8 tiles of 32, double-buffered.
// 8 warps: wm = wid&1 (rows 32), wn = wid>>1 (cols 64).
// acc = Ah*Bh + Ah*Bl + Al*Bh   (fp32 accum; lo*lo dropped ~2^-18)
// ---------------------------------------------------------------------------
#define MT 64
#define KT 32
#define PITCH 80          // bytes per smem row (32 bf16 + 8 pad)
// smem byte offsets
#define OFF_A   0         // A[s][t]: + (s*2+t)*5120     (64 rows * 80B)
#define OFF_B   20480     // B[s][t]: + (s*2+t)*20480    (256 rows * 80B)
#define OFF_IB  102400    // 256 floats
#define OFF_V   103424    // 256 floats
#define OFF_P   104448    // partial[64][4] floats
#define SMEM_TOTAL 105472

__global__ __launch_bounds__(256, 1) void k_main(const float* __restrict__ context,
                                                 const float* __restrict__ b_ctx,
                                                 const float* __restrict__ V) {
    extern __shared__ char smem[];
    uint32_t sb = smem_u32(smem);
    int tid = threadIdx.x;
    int wid = tid >> 5, lid = tid & 31;
    int wm = wid & 1, wn = wid >> 1;
    int b = blockIdx.y;
    int m0 = blockIdx.x * MT;

    float* ibs = (float*)(smem + OFF_IB);
    float* vvs = (float*)(smem + OFF_V);
    ibs[tid] = g_inp[b * HH + tid] + b_ctx[tid];
    vvs[tid] = V[tid];

    const float* ctx = context + ((long)b * SS + m0) * DD;

    // ---- A prefetch mapping: row = tid>>2, seg = tid&3 (8 floats each)
    int arow = tid >> 2, aseg = tid & 3;
    const float* aptr = ctx + arow * DD + aseg * 8;
    // ---- B cp.async mapping: 8 chunks of 16B per thread
    {
        int k0 = 0;
#pragma unroll
        for (int r = 0; r < 8; r++) {
            int idx = tid + 256 * r;
            int mat = idx >> 10, rem = idx & 1023;
            int row = rem >> 2, c = rem & 3;
            const __nv_bfloat16* src = (mat ? g_Bl : g_Bh) + row * DD + k0 + c * 8;
            uint32_t dst = sb + OFF_B + mat * 20480 + row * PITCH + c * 16;
            CP_ASYNC16(dst, src);
        }
        CP_COMMIT();
    }
    float4 a0 = *(const float4*)(aptr);
    float4 a1 = *(const float4*)(aptr + 4);

    float c[2][8][4];
#pragma unroll
    for (int mi = 0; mi < 2; mi++)
#pragma unroll
        for (int j = 0; j < 8; j++)
#pragma unroll
            for (int e = 0; e < 4; e++) c[mi][j][e] = 0.f;

    for (int kt = 0; kt < DD / KT; kt++) {
        int s = kt & 1;
        // ---- convert prefetched A (fp32 -> bf16 hi/lo) into stage s
        {
            float f[8] = {a0.x, a0.y, a0.z, a0.w, a1.x, a1.y, a1.z, a1.w};
            uint32_t hi[4], lo[4];
#pragma unroll
            for (int e = 0; e < 4; e++) {
                __nv_bfloat16 h0 = __float2bfloat16_rn(f[2*e]);
                __nv_bfloat16 h1 = __float2bfloat16_rn(f[2*e+1]);
                __nv_bfloat16 l0 = __float2bfloat16_rn(f[2*e]   - __bfloat162float(h0));
                __nv_bfloat16 l1 = __float2bfloat16_rn(f[2*e+1] - __bfloat162float(h1));
                hi[e] = (uint32_t)__bfloat16_as_ushort(h0) | ((uint32_t)__bfloat16_as_ushort(h1) << 16);
                lo[e] = (uint32_t)__bfloat16_as_ushort(l0) | ((uint32_t)__bfloat16_as_ushort(l1) << 16);
            }
            char* base = smem + OFF_A + s * 10240 + arow * PITCH + aseg * 16;
            *(uint4*)(base)         = make_uint4(hi[0], hi[1], hi[2], hi[3]);
            *(uint4*)(base + 5120)  = make_uint4(lo[0], lo[1], lo[2], lo[3]);
        }
        CP_WAIT0();
        __syncthreads();

        // ---- prefetch next stage
        if (kt < DD / KT - 1) {
            int k0 = (kt + 1) * KT;
#pragma unroll
            for (int r = 0; r < 8; r++) {
                int idx = tid + 256 * r;
                int mat = idx >> 10, rem = idx & 1023;
                int row = rem >> 2, cc = rem & 3;
                const __nv_bfloat16* src = (mat ? g_Bl : g_Bh) + row * DD + k0 + cc * 8;
                uint32_t dst = sb + OFF_B + (s ^ 1) * 2 * 20480 + mat * 20480 + row * PITCH + cc * 16;
                CP_ASYNC16(dst, src);
            }
            CP_COMMIT();
            const float* ap = ctx + arow * DD + k0 + aseg * 8;
            a0 = *(const float4*)(ap);
            a1 = *(const float4*)(ap + 4);
        }

        // ---- MMAs over stage s
        uint32_t abase = sb + OFF_A + s * 10240;
        uint32_t bbase = sb + OFF_B + s * 2 * 20480;
#pragma unroll
        for (int ks = 0; ks < 2; ks++) {
            uint32_t aH[2][4], aL[2][4], bH[4][4], bL[4][4];
            int arow_f = wm * 32 + (lid & 15);
            int acol_b = ks * 32 + (lid >> 4) * 16;
#pragma unroll
            for (int mi = 0; mi < 2; mi++) {
                uint32_t ad = abase + (arow_f + mi * 16) * PITCH + acol_b;
                LDSM4(aH[mi][0], aH[mi][1], aH[mi][2], aH[mi][3], ad);
                LDSM4(aL[mi][0], aL[mi][1], aL[mi][2], aL[mi][3], ad + 5120);
            }
            // x4 B load: matrices {0,1} = n-rows +0..7 (k halves),
            //            matrices {2,3} = n-rows +8..15  -> +8, NOT +16
            int brow_f = wn * 64 + (lid & 7) + ((lid >> 4) * 8);
            int bcol_b = ks * 32 + ((lid >> 3) & 1) * 16;
#pragma unroll
            for (int jp = 0; jp < 4; jp++) {
                uint32_t bd = bbase + (brow_f + jp * 16) * PITCH + bcol_b;
                LDSM4(bH[jp][0], bH[jp][1], bH[jp][2], bH[jp][3], bd);
                LDSM4(bL[jp][0], bL[jp][1], bL[jp][2], bL[jp][3], bd + 20480);
            }
#pragma unroll
            for (int mi = 0; mi < 2; mi++)
#pragma unroll
                for (int j = 0; j < 8; j++) {
                    uint32_t h0 = bH[j >> 1][(j & 1) * 2], h1 = bH[j >> 1][(j & 1) * 2 + 1];
                    uint32_t l0 = bL[j >> 1][(j & 1) * 2], l1 = bL[j >> 1][(j & 1) * 2 + 1];
                    MMA_BF16(c[mi][j], aH[mi], h0, h1);
                    MMA_BF16(c[mi][j], aH[mi], l0, l1);
                    MMA_BF16(c[mi][j], aL[mi], h0, h1);
                }
        }
    }

    // ---- epilogue: per-row tanh-dot with V
    // lane layout: rows = wm*32 + mi*16 + (lid>>2) + half*8; cols = wn*64 + j*8 + (lid&3)*2 + e
    {
        int q = lid & 3, g = lid >> 2;
        float ps[2][2] = {{0.f, 0.f}, {0.f, 0.f}};
#pragma unroll
        for (int mi = 0; mi < 2; mi++)
#pragma unroll
            for (int j = 0; j < 8; j++) {
                int h0 = wn * 64 + j * 8 + q * 2;
                ps[mi][0] += vvs[h0]   * tanhf(c[mi][j][0] + ibs[h0]);
                ps[mi][0] += vvs[h0+1] * tanhf(c[mi][j][1] + ibs[h0+1]);
                ps[mi][1] += vvs[h0]   * tanhf(c[mi][j][2] + ibs[h0]);
                ps[mi][1] += vvs[h0+1] * tanhf(c[mi][j][3] + ibs[h0+1]);
            }
#pragma unroll
        for (int off = 1; off <= 2; off <<= 1) {
#pragma unroll
            for (int mi = 0; mi < 2; mi++) {
                ps[mi][0] += __shfl_xor_sync(0xffffffffu, ps[mi][0], off);
                ps[mi][1] += __shfl_xor_sync(0xffffffffu, ps[mi][1], off);
            }
        }
        float* part = (float*)(smem + OFF_P);
        __syncthreads();
        if (q == 0) {
#pragma unroll
            for (int mi = 0; mi < 2; mi++) {
                part[(wm * 32 + mi * 16 + g) * 4 + wn]     = ps[mi][0];
                part[(wm * 32 + mi * 16 + g + 8) * 4 + wn] = ps[mi][1];
            }
        }
        __syncthreads();
        if (tid < MT) {
            float ssum = part[tid * 4] + part[tid * 4 + 1] + part[tid * 4 + 2] + part[tid * 4 + 3];
            g_att[b * SS + m0 + tid] = 10.f * tanhf(ssum);
        }
    }
}

// ---------------------------------------------------------------------------
// Kernel 4a: echo mask
// ---------------------------------------------------------------------------
__global__ void k_echo(const int* __restrict__ mask, float* __restrict__ out) {
    int i = blockIdx.x * blockDim.x + threadIdx.x;
    out[2 * BB + i] = mask[i] ? 1.f : 0.f;
}

// ---------------------------------------------------------------------------
// Kernel 4b: single-pass masked argmax + p = exp(max)/sum(exp(att)).
// att in [-10,10] so exp() cannot overflow.
// ---------------------------------------------------------------------------
__global__ __launch_bounds__(1024) void k_reduce(const int* __restrict__ mask,
                                                 float* __restrict__ out) {
    int b = blockIdx.x, tid = threadIdx.x;
    __shared__ float smax[1024], ssum[1024];
    __shared__ int   sidx[1024];

    float best = -INFINITY, se = 0.f;
    int bidx = 0x7fffffff;
    for (int s = tid; s < SS; s += 1024) {
        if (mask[b * SS + s]) {
            float v = g_att[b * SS + s];
            se += expf(v);
            if (v > best || (v == best && s < bidx)) { best = v; bidx = s; }
        }
    }
    smax[tid] = best; sidx[tid] = bidx; ssum[tid] = se;
    __syncthreads();
    for (int off = 512; off; off >>= 1) {
        if (tid < off) {
            float v = smax[tid + off]; int ix = sidx[tid + off];
            if (v > smax[tid] || (v == smax[tid] && ix < sidx[tid])) {
                smax[tid] = v; sidx[tid] = ix;
            }
            ssum[tid] += ssum[tid + off];
        }
        __syncthreads();
    }
    if (tid == 0) {
        float rowmax = smax[0];
        out[b]      = (float)((rowmax == -INFINITY) ? 0 : sidx[0]);
        out[BB + b] = expf(rowmax) / ssum[0];
    }
}

// ---------------------------------------------------------------------------
extern "C" void kernel_launch(void* const* d_in, const int* in_sizes, int n_in,
                              void* d_out, int out_size) {
    const float* x      = (const float*)d_in[0];
    const float* contex = (const float*)d_in[1];
    const int*   mask   = (const int*)  d_in[2];
    const float* W_in   = (const float*)d_in[3];
    const float* b_in   = (const float*)d_in[4];
    const float* W_ctx  = (const float*)d_in[5];
    const float* b_ctx  = (const float*)d_in[6];
    const float* V      = (const float*)d_in[7];
    float* out = (float*)d_out;

    cudaFuncSetAttribute(k_main, cudaFuncAttributeMaxDynamicSharedMemorySize, SMEM_TOTAL);

    k_inp<<<BB, HH>>>(x, W_in, b_in);
    k_wsplit<<<HH * DD / 256, 256>>>(W_ctx);
    k_main<<<dim3(SS / MT, BB), 256, SMEM_TOTAL>>>(contex, b_ctx, V);
    k_echo<<<BB * SS / 256, 256>>>(mask, out);
    k_reduce<<<BB, 1024>>>(mask, out);
}